// round 17
// baseline (speedup 1.0000x reference)
#include <cuda_runtime.h>
#include <cuda_bf16.h>
#include <cuda_fp16.h>
#include <math.h>
#include <stdint.h>

// Problem constants
#define BB 2
#define NN 4096
#define CC 512
#define HH 8
#define DD 64
#define MM (BB*NN)      // 8192
#define ADA6 (6*CC)     // 3072
#define NT64 (NN/64)    // 64 kv tiles max

// ---------------- scratch ----------------------------------------------------
__device__ float  g_ada[BB*ADA6];
__device__ __half g_qkv[MM*3*CC];       // qkv (fp16, q pre-scaled by 0.125*log2e)
__device__ __half g_o [MM*CC];          // attention out (fp16)
__device__ float  g_x1[MM*CC];          // residual stream (fp32)
__device__ __half g_h3[MM*CC];          // gelu out (fp16)
__device__ float2 g_st0[MM];            // LN stats of x
__device__ float2 g_st1[MM];            // LN stats of x1
__device__ int    g_kvidx[BB*NN];
__device__ int    g_kvcnt[BB];
// packed K/V fragment PAIRS: [b][h][tile][ks(4)][njp(4)][lane(32)] uint4
__device__ uint4  g_kp[BB*HH*NT64*4*4*32];
__device__ uint4  g_vp[BB*HH*NT64*4*4*32];
// packed weights (fp16 fragment pairs)
#define WP4_QKV  0
#define WP4_PROJ 98304
#define WP4_MLP1 131072
#define WP4_MLP2 163840
__device__ uint4  g_wp[196608];

#define ATTN_SMEM (2*1024*16)   // 32768

// ---------------- helpers ----------------------------------------------------
__device__ __forceinline__ uint32_t h2u(float a, float b) {
    __half2 h = __floats2half2_rn(a, b);
    return *(uint32_t*)&h;
}
__device__ __forceinline__ void mma_f16(float4& d, const uint32_t a[4],
                                        uint32_t b0, uint32_t b1) {
    asm volatile(
        "mma.sync.aligned.m16n8k16.row.col.f32.f16.f16.f32 "
        "{%0,%1,%2,%3}, {%4,%5,%6,%7}, {%8,%9}, {%0,%1,%2,%3};\n"
        : "+f"(d.x), "+f"(d.y), "+f"(d.z), "+f"(d.w)
        : "r"(a[0]), "r"(a[1]), "r"(a[2]), "r"(a[3]), "r"(b0), "r"(b1));
}
__device__ __forceinline__ uint32_t s2u(const void* p) {
    uint32_t a;
    asm("{ .reg .u64 t; cvta.to.shared.u64 t, %1; cvt.u32.u64 %0, t; }" : "=r"(a) : "l"(p));
    return a;
}
__device__ __forceinline__ void cp_async16(uint32_t dst, const void* src) {
    asm volatile("cp.async.cg.shared.global [%0], [%1], 16;" :: "r"(dst), "l"(src));
}
__device__ __forceinline__ void cp_commit() { asm volatile("cp.async.commit_group;" ::: "memory"); }
template<int NG> __device__ __forceinline__ void cp_wait() {
    asm volatile("cp.async.wait_group %0;" :: "n"(NG) : "memory");
}

// ---------------- ada = silu(cond) @ ada_w + ada_b ---------------------------
__global__ void ada_kernel(const float* __restrict__ cond,
                           const float* __restrict__ ada_w,
                           const float* __restrict__ ada_b) {
    int b = blockIdx.x / 12;
    int j = (blockIdx.x % 12) * 256 + threadIdx.x;
    __shared__ float sc[CC];
    for (int t = threadIdx.x; t < CC; t += 256) {
        float x = cond[b*CC + t];
        sc[t] = x / (1.0f + expf(-x));
    }
    __syncthreads();
    float acc = ada_b[j];
    #pragma unroll 8
    for (int c = 0; c < CC; c++) acc += sc[c] * ada_w[c*ADA6 + j];
    g_ada[b*ADA6 + j] = acc;
}

// ---------------- row LN stats: one warp per row ------------------------------
__global__ void stats_kernel(const float* __restrict__ X, float2* __restrict__ st) {
    int row = blockIdx.x*8 + (threadIdx.x >> 5);
    int lane = threadIdx.x & 31;
    const float4* xr = (const float4*)(X + (size_t)row*CC);
    float s = 0.f, sq = 0.f;
    #pragma unroll
    for (int i = 0; i < 4; i++) {
        float4 v = xr[lane + i*32];
        s  += v.x + v.y + v.z + v.w;
        sq += v.x*v.x + v.y*v.y + v.z*v.z + v.w*v.w;
    }
    #pragma unroll
    for (int off = 16; off > 0; off >>= 1) {
        s  += __shfl_xor_sync(0xffffffffu, s,  off);
        sq += __shfl_xor_sync(0xffffffffu, sq, off);
    }
    if (lane == 0) {
        float mean = s * (1.0f/CC);
        float var  = sq * (1.0f/CC) - mean*mean;
        st[row] = make_float2(mean, rsqrtf(var + 1e-6f));
    }
}

// ---------------- mask compaction (shfl-scan) ---------------------------------
__global__ void compact_kernel(const int* __restrict__ mask) {
    int b = blockIdx.x;
    int tid = threadIdx.x;          // 1024
    int warp = tid >> 5, lane = tid & 31;
    int base = b*NN;
    int loc[4]; int cnt = 0;
    #pragma unroll
    for (int q = 0; q < 4; q++) {
        int n = tid*4 + q;
        if (mask[base + n] == 1) loc[cnt++] = n;
    }
    int inc = cnt;
    #pragma unroll
    for (int off = 1; off < 32; off <<= 1) {
        int v = __shfl_up_sync(0xffffffffu, inc, off);
        if (lane >= off) inc += v;
    }
    __shared__ int wsum[32];
    if (lane == 31) wsum[warp] = inc;
    __syncthreads();
    if (warp == 0) {
        int v = wsum[lane];
        int s = v;
        #pragma unroll
        for (int off = 1; off < 32; off <<= 1) {
            int u = __shfl_up_sync(0xffffffffu, s, off);
            if (lane >= off) s += u;
        }
        wsum[lane] = s - v;
        if (lane == 31) g_kvcnt[b] = s;
    }
    __syncthreads();
    int start = wsum[warp] + inc - cnt;
    for (int i = 0; i < cnt; i++) g_kvidx[base + start + i] = loc[i];
}

// ---------------- weight pack (all 4 weights, one launch) ---------------------
__global__ void wpack_f16(const float* __restrict__ W0, const float* __restrict__ W1,
                          const float* __restrict__ W2, const float* __restrict__ W3) {
    __shared__ float ws[16][65];
    int k16 = blockIdx.x, nb = blockIdx.y;
    const float* W; int N; size_t off; int nbl;
    if (nb < 24)      { W = W0; N = 3*CC; off = WP4_QKV;  nbl = nb; }
    else if (nb < 32) { W = W1; N = CC;   off = WP4_PROJ; nbl = nb - 24; }
    else if (nb < 40) { W = W2; N = CC;   off = WP4_MLP1; nbl = nb - 32; }
    else              { W = W3; N = CC;   off = WP4_MLP2; nbl = nb - 40; }
    int tid = threadIdx.x;
    for (int i = tid; i < 16*64; i += 256) {
        int k = i >> 6, n = i & 63;
        ws[k][n] = W[(size_t)(k16*16 + k)*N + nbl*64 + n];
    }
    __syncthreads();
    if (tid < 128) {
        int nfp = tid >> 5, lane = tid & 31;
        int lr = lane >> 2, k0 = 2*(lane & 3);
        int n0 = nfp*16 + lr, n1 = n0 + 8;
        uint4 u;
        u.x = h2u(ws[k0][n0],   ws[k0+1][n0]);
        u.y = h2u(ws[k0+8][n0], ws[k0+9][n0]);
        u.z = h2u(ws[k0][n1],   ws[k0+1][n1]);
        u.w = h2u(ws[k0+8][n1], ws[k0+9][n1]);
        g_wp[off + ((size_t)k16*(N>>4) + nbl*4 + nfp)*32 + lane] = u;
    }
}

// ---------------- FP16 tensor-core GEMM, optional fused LN+modulate -----------
// LNA=1: A is fp32 X; apply (x-mean)*rstd*(1+sc)+sh inline (stats + ada vecs).
template<int EPI, int LNA>
__global__ __launch_bounds__(256, 2)
void gemm_f16(const void* __restrict__ Ain, const uint4* __restrict__ Wp,
              const float* __restrict__ bias,
              const float* __restrict__ resid,
              const float* __restrict__ gate,
              const float2* __restrict__ stats,
              const float* __restrict__ adav, int shOff, int scOff,
              void* __restrict__ CoutV, int N) {
    __shared__ uint4 Asp[2][512];
    int tid  = threadIdx.x;
    int warp = tid >> 5, lane = tid & 31;
    int wg = warp >> 2, wn4 = warp & 3;
    int m0 = blockIdx.y*128, n0 = blockIdx.x*128;

    // per-slot constants (2 loader slots per thread)
    int rS0[2], rS1[2], ckoS[2];
    #pragma unroll
    for (int j = 0; j < 2; j++) {
        int s = tid + j*256;
        int rg = s >> 5, ln = s & 31;
        int mg = rg >> 1, ksl = rg & 1;
        rS0[j] = m0 + mg*16 + (ln >> 2);
        rS1[j] = rS0[j] + 8;
        ckoS[j] = ksl*16 + 2*(ln & 3);
    }
    float2 stv0[2], stv1[2];
    const float* scp = nullptr;
    const float* shp = nullptr;
    if (LNA) {
        #pragma unroll
        for (int j = 0; j < 2; j++) {
            stv0[j] = stats[rS0[j]];
            stv1[j] = stats[rS1[j]];
        }
        int bb = rS0[0] >> 12;
        scp = adav + bb*ADA6 + scOff;
        shp = adav + bb*ADA6 + shOff;
    }

    auto loadA = [&](int kt, uint4& o0, uint4& o1) {
        #pragma unroll
        for (int j = 0; j < 2; j++) {
            int ck = kt*32 + ckoS[j];
            uint4 v;
            if (LNA) {
                const float* Xf = (const float*)Ain;
                float2 x00 = *(const float2*)&Xf[(size_t)rS0[j]*CC + ck];
                float2 x10 = *(const float2*)&Xf[(size_t)rS1[j]*CC + ck];
                float2 x01 = *(const float2*)&Xf[(size_t)rS0[j]*CC + ck + 8];
                float2 x11 = *(const float2*)&Xf[(size_t)rS1[j]*CC + ck + 8];
                float2 sc0 = *(const float2*)&scp[ck];
                float2 sc1 = *(const float2*)&scp[ck + 8];
                float2 sh0 = *(const float2*)&shp[ck];
                float2 sh1 = *(const float2*)&shp[ck + 8];
                float a0 = 1.f + sc0.x, a1 = 1.f + sc0.y;
                float a2 = 1.f + sc1.x, a3 = 1.f + sc1.y;
                float m0v = stv0[j].x, r0v = stv0[j].y;
                float m1v = stv1[j].x, r1v = stv1[j].y;
                v.x = h2u((x00.x - m0v)*r0v*a0 + sh0.x, (x00.y - m0v)*r0v*a1 + sh0.y);
                v.y = h2u((x10.x - m1v)*r1v*a0 + sh0.x, (x10.y - m1v)*r1v*a1 + sh0.y);
                v.z = h2u((x01.x - m0v)*r0v*a2 + sh1.x, (x01.y - m0v)*r0v*a3 + sh1.y);
                v.w = h2u((x11.x - m1v)*r1v*a2 + sh1.x, (x11.y - m1v)*r1v*a3 + sh1.y);
            } else {
                const __half* A = (const __half*)Ain;
                v.x = *(const uint32_t*)&A[(size_t)rS0[j]*CC + ck];
                v.y = *(const uint32_t*)&A[(size_t)rS1[j]*CC + ck];
                v.z = *(const uint32_t*)&A[(size_t)rS0[j]*CC + ck + 8];
                v.w = *(const uint32_t*)&A[(size_t)rS1[j]*CC + ck + 8];
            }
            if (j) o1 = v; else o0 = v;
        }
    };

    const uint4* wp0 = Wp + ((size_t)(n0 >> 4) + wn4*2)*32 + lane;
    size_t wstride = (size_t)(N >> 4) * 32;

    float4 acc[4][4];
    #pragma unroll
    for (int i = 0; i < 4; i++)
        #pragma unroll
        for (int j = 0; j < 4; j++) acc[i][j] = make_float4(0.f,0.f,0.f,0.f);

    int s0 = tid, s1 = tid + 256;
    uint4 pa0, pa1;
    loadA(0, pa0, pa1);
    Asp[0][s0] = pa0; Asp[0][s1] = pa1;
    uint4 bf[2][2][2];
    #pragma unroll
    for (int ks = 0; ks < 2; ks++)
        #pragma unroll
        for (int p = 0; p < 2; p++)
            bf[0][ks][p] = __ldg(wp0 + (size_t)ks*wstride + (size_t)p*32);
    __syncthreads();

    for (int kt = 0; kt < 16; kt++) {
        int cur = kt & 1;
        if (kt < 15) {
            loadA(kt + 1, pa0, pa1);
            #pragma unroll
            for (int ks = 0; ks < 2; ks++)
                #pragma unroll
                for (int p = 0; p < 2; p++)
                    bf[cur^1][ks][p] =
                        __ldg(wp0 + ((size_t)(kt+1)*2 + ks)*wstride + (size_t)p*32);
        }
        #pragma unroll
        for (int ks = 0; ks < 2; ks++) {
            #pragma unroll
            for (int mi = 0; mi < 4; mi++) {
                uint4 af4 = Asp[cur][(((wg*4 + mi)*2 + ks) << 5) + lane];
                uint32_t afr[4] = { af4.x, af4.y, af4.z, af4.w };
                #pragma unroll
                for (int p = 0; p < 2; p++) {
                    mma_f16(acc[mi][2*p],   afr, bf[cur][ks][p].x, bf[cur][ks][p].y);
                    mma_f16(acc[mi][2*p+1], afr, bf[cur][ks][p].z, bf[cur][ks][p].w);
                }
            }
        }
        if (kt < 15) {
            Asp[cur^1][s0] = pa0;
            Asp[cur^1][s1] = pa1;
        }
        __syncthreads();
    }

    int wm = wg*64, wn = wn4*32;
    int lr = lane >> 2, lc = lane & 3;
    #pragma unroll
    for (int mi = 0; mi < 4; mi++) {
        int r0 = m0 + wm + mi*16 + lr;
        int r1 = r0 + 8;
        int b0i = r0 >> 12, b1i = r1 >> 12;
        #pragma unroll
        for (int nj = 0; nj < 4; nj++) {
            int c = n0 + wn + nj*8 + 2*lc;
            float4 d = acc[mi][nj];
            float bx = bias[c], by = bias[c+1];
            float vx = d.x + bx, vy = d.y + by;
            float wx = d.z + bx, wy = d.w + by;
            if (EPI == 0) {
                // fold D^-0.5 * log2(e) into q (softmax runs in exp2 domain)
                float qs = (c < CC) ? 0.125f * 1.4426950408889634f : 1.0f;
                vx *= qs; vy *= qs; wx *= qs; wy *= qs;
                __half* Ch = (__half*)CoutV;
                *(uint32_t*)&Ch[(size_t)r0*N + c] = h2u(vx, vy);
                *(uint32_t*)&Ch[(size_t)r1*N + c] = h2u(wx, wy);
            } else if (EPI == 1) {
                vx = 0.5f*vx*(1.0f + erff(vx*0.70710678118654752f));
                vy = 0.5f*vy*(1.0f + erff(vy*0.70710678118654752f));
                wx = 0.5f*wx*(1.0f + erff(wx*0.70710678118654752f));
                wy = 0.5f*wy*(1.0f + erff(wy*0.70710678118654752f));
                __half* Ch = (__half*)CoutV;
                *(uint32_t*)&Ch[(size_t)r0*N + c] = h2u(vx, vy);
                *(uint32_t*)&Ch[(size_t)r1*N + c] = h2u(wx, wy);
            } else {
                float gx0 = gate[(size_t)b0i*ADA6 + c], gy0 = gate[(size_t)b0i*ADA6 + c + 1];
                float gx1 = gate[(size_t)b1i*ADA6 + c], gy1 = gate[(size_t)b1i*ADA6 + c + 1];
                float* Cf = (float*)CoutV;
                *(float2*)&Cf[(size_t)r0*N + c] =
                    make_float2(resid[(size_t)r0*CC + c]     + gx0*vx,
                                resid[(size_t)r0*CC + c + 1] + gy0*vy);
                *(float2*)&Cf[(size_t)r1*N + c] =
                    make_float2(resid[(size_t)r1*CC + c]     + gx1*wx,
                                resid[(size_t)r1*CC + c + 1] + gy1*wy);
            }
        }
    }
}

// ---------------- KV pack: gather fp16 + fragment-pair permute ----------------
__global__ __launch_bounds__(256)
void kv_pack_kernel() {
    __shared__ __half Ks[64][72];
    __shared__ __half Vs[64][72];
    int t = blockIdx.x, h = blockIdx.y, b = blockIdx.z;
    int nk = g_kvcnt[b];
    int ntiles = (nk + 63) >> 6;
    if (t >= ntiles) return;
    int tid = threadIdx.x;

    {
        int row = tid >> 2, q4 = tid & 3;
        int slot = t*64 + row;
        if (slot < nk) {
            int n = g_kvidx[b*NN + slot];
            const __half* base = g_qkv + (size_t)(b*NN + n)*(3*CC) + h*DD + q4*16;
            *(uint4*)&Ks[row][q4*16]     = *(const uint4*)(base + CC);
            *(uint4*)&Ks[row][q4*16 + 8] = *(const uint4*)(base + CC + 8);
            *(uint4*)&Vs[row][q4*16]     = *(const uint4*)(base + 2*CC);
            *(uint4*)&Vs[row][q4*16 + 8] = *(const uint4*)(base + 2*CC + 8);
        } else {
            uint4 z = make_uint4(0,0,0,0);
            *(uint4*)&Ks[row][q4*16] = z; *(uint4*)&Ks[row][q4*16 + 8] = z;
            *(uint4*)&Vs[row][q4*16] = z; *(uint4*)&Vs[row][q4*16 + 8] = z;
        }
    }
    __syncthreads();

    int g = tid >> 5, lane = tid & 31;
    int lr = lane >> 2, lc = lane & 3;
    size_t tb = ((size_t)(b*HH + h)*NT64 + t) * 512;
    if (g < 4) {
        int n0 = g*16 + lr, n1 = n0 + 8;
        #pragma unroll
        for (int ks = 0; ks < 4; ks++) {
            int k0 = ks*16 + 2*lc;
            uint4 u;
            u.x = *(const uint32_t*)&Ks[n0][k0];
            u.y = *(const uint32_t*)&Ks[n0][k0 + 8];
            u.z = *(const uint32_t*)&Ks[n1][k0];
            u.w = *(const uint32_t*)&Ks[n1][k0 + 8];
            g_kp[tb + (ks*4 + g)*32 + lane] = u;
        }
    } else {
        int gg = g - 4;
        int nd0 = gg*16 + lr, nd1 = nd0 + 8;
        #pragma unroll
        for (int ks = 0; ks < 4; ks++) {
            int k0 = ks*16 + 2*lc;
            uint4 u;
            u.x = h2u(__half2float(Vs[k0][nd0]),   __half2float(Vs[k0+1][nd0]));
            u.y = h2u(__half2float(Vs[k0+8][nd0]), __half2float(Vs[k0+9][nd0]));
            u.z = h2u(__half2float(Vs[k0][nd1]),   __half2float(Vs[k0+1][nd1]));
            u.w = h2u(__half2float(Vs[k0+8][nd1]), __half2float(Vs[k0+9][nd1]));
            g_vp[tb + (ks*4 + gg)*32 + lane] = u;
        }
    }
}

// ---------------- FP16 flash attention (cp.async, P in registers) -------------
__global__ __launch_bounds__(256, 2)
void attn_f16() {
    extern __shared__ __align__(16) char smraw[];
    uint4* KV = (uint4*)smraw;                          // [2][1024]

    int qb = blockIdx.x, h = blockIdx.y, b = blockIdx.z;
    int tid = threadIdx.x;
    int warp = tid >> 5, lane = tid & 31;
    int lr = lane >> 2, lc = lane & 3;
    uint32_t kvsm = s2u(KV);

    uint32_t qf[4][4];
    {
        const __half* q0 = g_qkv + (size_t)(b*NN + qb*128 + warp*16 + lr)*(3*CC) + h*DD;
        const __half* q1 = q0 + (size_t)8*(3*CC);
        #pragma unroll
        for (int ks = 0; ks < 4; ks++) {
            int k0 = ks*16 + 2*lc;
            qf[ks][0] = *(const uint32_t*)&q0[k0];
            qf[ks][1] = *(const uint32_t*)&q1[k0];
            qf[ks][2] = *(const uint32_t*)&q0[k0 + 8];
            qf[ks][3] = *(const uint32_t*)&q1[k0 + 8];
        }
    }

    float4 o[8];
    #pragma unroll
    for (int dn = 0; dn < 8; dn++) o[dn] = make_float4(0.f,0.f,0.f,0.f);
    float m0 = -INFINITY, m1 = -INFINITY, l0 = 0.f, l1 = 0.f;

    int nk = g_kvcnt[b];
    int ntiles = (nk + 63) >> 6;
    const uint4* kpb = g_kp + ((size_t)(b*HH + h))*NT64*512;
    const uint4* vpb = g_vp + ((size_t)(b*HH + h))*NT64*512;

    auto issue = [&](int t, int buf) {
        const uint4* kp = kpb + (size_t)t*512;
        const uint4* vp = vpb + (size_t)t*512;
        uint32_t dst = kvsm + (uint32_t)buf*16384;
        #pragma unroll
        for (int j = 0; j < 2; j++) {
            int idx = tid + j*256;
            cp_async16(dst + idx*16,          kp + idx);
            cp_async16(dst + (idx + 512)*16,  vp + idx);
        }
        cp_commit();
    };

    issue(0, 0);
    if (ntiles > 1) issue(1, 1);

    for (int t = 0; t < ntiles; t++) {
        if (t + 1 < ntiles) cp_wait<1>(); else cp_wait<0>();
        __syncthreads();
        int buf = t & 1;
        const uint4* kb = &KV[buf*1024];
        const uint4* vb = &KV[buf*1024 + 512];

        float4 s[8];
        #pragma unroll
        for (int nj = 0; nj < 8; nj++) s[nj] = make_float4(0.f,0.f,0.f,0.f);
        #pragma unroll
        for (int ks = 0; ks < 4; ks++) {
            #pragma unroll
            for (int p = 0; p < 4; p++) {
                uint4 kk = kb[(ks*4 + p)*32 + lane];
                mma_f16(s[2*p],   qf[ks], kk.x, kk.y);
                mma_f16(s[2*p+1], qf[ks], kk.z, kk.w);
            }
        }

        int valid = nk - t*64;
        if (valid < 64) {
            #pragma unroll
            for (int nj = 0; nj < 8; nj++) {
                int c0 = nj*8 + 2*lc;
                if (c0     >= valid) { s[nj].x = -1e30f; s[nj].z = -1e30f; }
                if (c0 + 1 >= valid) { s[nj].y = -1e30f; s[nj].w = -1e30f; }
            }
        }

        float mx0 = -1e30f, mx1 = -1e30f;
        #pragma unroll
        for (int nj = 0; nj < 8; nj++) {
            mx0 = fmaxf(mx0, fmaxf(s[nj].x, s[nj].y));
            mx1 = fmaxf(mx1, fmaxf(s[nj].z, s[nj].w));
        }
        mx0 = fmaxf(mx0, __shfl_xor_sync(0xffffffffu, mx0, 1));
        mx0 = fmaxf(mx0, __shfl_xor_sync(0xffffffffu, mx0, 2));
        mx1 = fmaxf(mx1, __shfl_xor_sync(0xffffffffu, mx1, 1));
        mx1 = fmaxf(mx1, __shfl_xor_sync(0xffffffffu, mx1, 2));
        float mn0 = fmaxf(m0, mx0), mn1 = fmaxf(m1, mx1);
        float cr0 = exp2f(m0 - mn0), cr1 = exp2f(m1 - mn1);
        m0 = mn0; m1 = mn1;
        float sum0 = 0.f, sum1 = 0.f;
        #pragma unroll
        for (int nj = 0; nj < 8; nj++) {
            s[nj].x = exp2f(s[nj].x - mn0); sum0 += s[nj].x;
            s[nj].y = exp2f(s[nj].y - mn0); sum0 += s[nj].y;
            s[nj].z = exp2f(s[nj].z - mn1); sum1 += s[nj].z;
            s[nj].w = exp2f(s[nj].w - mn1); sum1 += s[nj].w;
        }
        sum0 += __shfl_xor_sync(0xffffffffu, sum0, 1);
        sum0 += __shfl_xor_sync(0xffffffffu, sum0, 2);
        sum1 += __shfl_xor_sync(0xffffffffu, sum1, 1);
        sum1 += __shfl_xor_sync(0xffffffffu, sum1, 2);
        l0 = l0*cr0 + sum0;
        l1 = l1*cr1 + sum1;
        #pragma unroll
        for (int dn = 0; dn < 8; dn++) {
            o[dn].x *= cr0; o[dn].y *= cr0;
            o[dn].z *= cr1; o[dn].w *= cr1;
        }

        // O += P @ V : P A-frags built directly from S C-frags
        #pragma unroll
        for (int ks = 0; ks < 4; ks++) {
            uint32_t pf[4];
            pf[0] = h2u(s[2*ks].x,   s[2*ks].y);
            pf[1] = h2u(s[2*ks].z,   s[2*ks].w);
            pf[2] = h2u(s[2*ks+1].x, s[2*ks+1].y);
            pf[3] = h2u(s[2*ks+1].z, s[2*ks+1].w);
            #pragma unroll
            for (int p = 0; p < 4; p++) {
                uint4 vv = vb[(ks*4 + p)*32 + lane];
                mma_f16(o[2*p],   pf, vv.x, vv.y);
                mma_f16(o[2*p+1], pf, vv.z, vv.w);
            }
        }

        __syncthreads();
        if (t + 2 < ntiles) issue(t + 2, buf);
    }

    float invl0 = 1.0f / l0, invl1 = 1.0f / l1;
    int r0 = qb*128 + warp*16 + lr;
    __half* orow0 = g_o + (size_t)(b*NN + r0)*CC + h*DD;
    __half* orow1 = orow0 + (size_t)8*CC;
    #pragma unroll
    for (int dn = 0; dn < 8; dn++) {
        int c = dn*8 + 2*lc;
        *(uint32_t*)&orow0[c] = h2u(o[dn].x*invl0, o[dn].y*invl0);
        *(uint32_t*)&orow1[c] = h2u(o[dn].z*invl1, o[dn].w*invl1);
    }
}

// ---------------------------------------------------------------------------
extern "C" void kernel_launch(void* const* d_in, const int* in_sizes, int n_in,
                              void* d_out, int out_size) {
    const float* x      = (const float*)d_in[0];
    const float* cond   = (const float*)d_in[1];
    const int*   mask   = (const int*)  d_in[2];
    const float* qkv_w  = (const float*)d_in[3];
    const float* qkv_b  = (const float*)d_in[4];
    const float* proj_w = (const float*)d_in[5];
    const float* proj_b = (const float*)d_in[6];
    const float* ada_w  = (const float*)d_in[7];
    const float* ada_b  = (const float*)d_in[8];
    const float* mlp_w1 = (const float*)d_in[9];
    const float* mlp_b1 = (const float*)d_in[10];
    const float* mlp_w2 = (const float*)d_in[11];
    const float* mlp_b2 = (const float*)d_in[12];
    float* out = (float*)d_out;

    float *p_ada, *p_x1;
    __half *p_qkv, *p_o, *p_h3;
    uint4 *p_wp;
    float2 *p_st0, *p_st1;
    cudaGetSymbolAddress((void**)&p_ada, g_ada);
    cudaGetSymbolAddress((void**)&p_qkv, g_qkv);
    cudaGetSymbolAddress((void**)&p_o,   g_o);
    cudaGetSymbolAddress((void**)&p_x1,  g_x1);
    cudaGetSymbolAddress((void**)&p_h3,  g_h3);
    cudaGetSymbolAddress((void**)&p_wp,  g_wp);
    cudaGetSymbolAddress((void**)&p_st0, g_st0);
    cudaGetSymbolAddress((void**)&p_st1, g_st1);

    cudaFuncSetAttribute(attn_f16, cudaFuncAttributeMaxDynamicSharedMemorySize, ATTN_SMEM);

    // 0. weight packs
    wpack_f16<<<dim3(32, 48), 256>>>(qkv_w, proj_w, mlp_w1, mlp_w2);
    // 1. adaLN vector
    ada_kernel<<<BB*12, 256>>>(cond, ada_w, ada_b);
    // 2. compact unmasked keys (exact: -10000 underflows to 0 in softmax)
    compact_kernel<<<BB, 1024>>>(mask);
    // 3. LN stats of x
    stats_kernel<<<MM/8, 256>>>(x, p_st0);
    // 4. qkv GEMM with fused LN+modulate (MSA: sh@0, sc@512) -> fp16, q scaled
    gemm_f16<0,1><<<dim3(12, 64), 256>>>(x, p_wp + WP4_QKV, qkv_b, nullptr, nullptr,
                                         p_st0, p_ada, 0, CC, p_qkv, 3*CC);
    // 5. pack compacted K/V
    kv_pack_kernel<<<dim3(NT64, HH, BB), 256>>>();
    // 6. attention
    attn_f16<<<dim3(NN/128, HH, BB), 256, ATTN_SMEM>>>();
    // 7. proj GEMM + gated residual (g_msa @1024) -> fp32 x1
    gemm_f16<2,0><<<dim3(4, 64), 256>>>(p_o, p_wp + WP4_PROJ, proj_b, x, p_ada + 2*CC,
                                        nullptr, nullptr, 0, 0, p_x1, CC);
    // 8. LN stats of x1
    stats_kernel<<<MM/8, 256>>>(p_x1, p_st1);
    // 9. mlp1 GEMM with fused LN+modulate (MLP: sh@1536, sc@2048) + GELU -> fp16
    gemm_f16<1,1><<<dim3(4, 64), 256>>>(p_x1, p_wp + WP4_MLP1, mlp_b1, nullptr, nullptr,
                                        p_st1, p_ada, 3*CC, 4*CC, p_h3, CC);
    // 10. mlp2 GEMM + gated residual (g_mlp @2560) -> d_out (fp32)
    gemm_f16<2,0><<<dim3(4, 64), 256>>>(p_h3, p_wp + WP4_MLP2, mlp_b2, p_x1, p_ada + 5*CC,
                                        nullptr, nullptr, 0, 0, out, CC);
}